// round 5
// baseline (speedup 1.0000x reference)
#include <cuda_runtime.h>
#include <cstdint>
#include <cstddef>

#define NB 4
#define NN 2048
#define CTAB 74                 // CTAs per batch
#define NCTA (NB * CTAB)        // 296 = 2 * 148 SMs exactly
#define TPB 448                 // 14 warps: 7 pair-groups x 2 halves
#define PRG 7
#define CPC 28                  // columns per CTA (last CTA of batch: 4)
#define NITS_K 50
#define TC 4

typedef unsigned long long u64;

constexpr float C_EPS  = 0.1f;
constexpr float C_TOL  = 1e-3f;
constexpr float C_L2E  = 1.4426950408889634f;
constexpr float C_KK   = C_L2E / C_EPS;          // log2(e)/eps
constexpr float C_2K   = 2.0f * C_KK;
constexpr float C_INVK = C_EPS / C_L2E;
constexpr float C_LN2  = 0.6931471805599453f;
constexpr float C_AL2E = -2.0f;                  // log2(1/4) = alpha*log2(e)

struct ScratchT {
    unsigned barcnt;
    unsigned pad[31];
    float AU[NB * NN];                // u'-form A potentials
    float BU[NB * NN];                // u'-form B potentials
    float errA[2 * NITS_K * NB];
    float errB[2 * NITS_K * NB];
    unsigned mvA[2 * NITS_K * NB];
    unsigned mvB[2 * NITS_K * NB];
    float cost[2 * NB];
    float cham[2 * NB];
};
__device__ ScratchT g_s;

__device__ __forceinline__ float ex2f_(float x) {
    float y; asm("ex2.approx.ftz.f32 %0, %1;" : "=f"(y) : "f"(x)); return y;
}
__device__ __forceinline__ float lg2f_(float x) {
    float y; asm("lg2.approx.f32 %0, %1;" : "=f"(y) : "f"(x)); return y;
}
__device__ __forceinline__ u64 pk2(float lo, float hi) {
    u64 r; asm("mov.b64 %0, {%1, %2};" : "=l"(r) : "f"(lo), "f"(hi)); return r;
}
__device__ __forceinline__ void upk(u64 v, float& lo, float& hi) {
    asm("mov.b64 {%0, %1}, %2;" : "=f"(lo), "=f"(hi) : "l"(v));
}
__device__ __forceinline__ u64 pfma(u64 a, u64 b, u64 c) {
    u64 d; asm("fma.rn.f32x2 %0, %1, %2, %3;" : "=l"(d) : "l"(a), "l"(b), "l"(c)); return d;
}
__device__ __forceinline__ u64 padd(u64 a, u64 b) {
    u64 d; asm("add.rn.f32x2 %0, %1, %2;" : "=l"(d) : "l"(a), "l"(b)); return d;
}
__device__ __forceinline__ unsigned encf(float f) {
    unsigned u = __float_as_uint(f);
    return (u & 0x80000000u) ? ~u : (u | 0x80000000u);
}
__device__ __forceinline__ float decf(unsigned e) {
    return (e & 0x80000000u) ? __uint_as_float(e & 0x7fffffffu) : __uint_as_float(~e);
}

// grid barrier: all 296 CTAs co-resident (exactly 2/SM), hot-spin on L2
__device__ __forceinline__ void grid_barrier(unsigned& lb) {
    __syncthreads();
    lb++;
    if (threadIdx.x == 0) {
        unsigned target = lb * (unsigned)NCTA;
        asm volatile("red.release.gpu.global.add.u32 [%0], %1;"
                     :: "l"(&g_s.barcnt), "r"(1u) : "memory");
        unsigned v;
        do {
            asm volatile("ld.acquire.gpu.global.u32 %0, [%1];"
                         : "=r"(v) : "l"(&g_s.barcnt) : "memory");
        } while (v < target);
    }
    __syncthreads();
}

// One Sinkhorn half-update, log2 domain, u'-form potentials:
//   stored u'_j = (v_j + alpha)*log2e - k*|q_j|^2
//   v_j = -ln2*(Mv + log2 sum_i 2^(u'_i + 2k r_i.q_j - k|q_j|^2 - Mv))
//   Mv = max_i p_i,  p_i = (v_i + alpha)*log2e  (writers maintain via atomicMax)
__device__ void half_update(
    const float* rX, const float* rY, const float* rZ,
    const float* cX, const float* cY, const float* cZ,
    float* sU, float* sPart,
    const float* srcU, float* dstU,
    const unsigned* mvSrc, unsigned* mvDst, float* errSlot,
    bool firstSrc, bool firstDst, int colbase)
{
    const int tid = threadIdx.x;

    if (firstSrc) {
        for (int t = tid; t < NN; t += TPB) {
            float x = rX[t], y = rY[t], z = rZ[t];
            sU[t] = C_AL2E - C_KK * fmaf(x, x, fmaf(y, y, z * z));
        }
    } else {
        for (int t = tid; t < NN; t += TPB) sU[t] = __ldcg(srcU + t);
    }
    const float Mv = firstSrc ? C_AL2E : decf(__ldcg(mvSrc));
    __syncthreads();

    const int wid = tid >> 5, lane = tid & 31;
    const int pr = wid >> 1, h = wid & 1;
    const int j0 = colbase + pr * TC;
    const bool valid = (j0 < NN);

    u64 qx2[TC], qy2[TC], qz2[TC], dj2[TC];
    float qqv[TC], sal[TC], sah[TC];
    if (valid) {
#pragma unroll
        for (int t = 0; t < TC; t++) {
            float qx = cX[j0 + t], qy = cY[j0 + t], qz = cZ[j0 + t];
            float qq = fmaf(qx, qx, fmaf(qy, qy, qz * qz));
            qqv[t] = qq;
            float sx = qx * C_2K, sy = qy * C_2K, sz = qz * C_2K;
            float dj = -C_KK * qq - Mv;
            qx2[t] = pk2(sx, sx); qy2[t] = pk2(sy, sy); qz2[t] = pk2(sz, sz);
            dj2[t] = pk2(dj, dj);
            sal[t] = 0.f; sah[t] = 0.f;
        }

        const float2* pX = (const float2*)rX;
        const float2* pY = (const float2*)rY;
        const float2* pZ = (const float2*)rZ;
        const float2* pU = (const float2*)sU;
        int idx = h * (NN / 4) + lane;
#pragma unroll 4
        for (int k = 0; k < NN / 128; k++, idx += 32) {
            float2 x2 = pX[idx], y2 = pY[idx], z2 = pZ[idx], u2 = pU[idx];
            u64 X2 = pk2(x2.x, x2.y), Y2 = pk2(y2.x, y2.y);
            u64 Z2 = pk2(z2.x, z2.y), U2 = pk2(u2.x, u2.y);
#pragma unroll
            for (int t = 0; t < TC; t++) {
                u64 w = padd(U2, dj2[t]);
                w = pfma(Z2, qz2[t], w);
                w = pfma(Y2, qy2[t], w);
                w = pfma(X2, qx2[t], w);
                float lo, hi; upk(w, lo, hi);
                sal[t] += ex2f_(lo);
                sah[t] += ex2f_(hi);
            }
        }
#pragma unroll
        for (int t = 0; t < TC; t++) sal[t] += sah[t];
#pragma unroll
        for (int o = 16; o > 0; o >>= 1)
#pragma unroll
            for (int t = 0; t < TC; t++)
                sal[t] += __shfl_xor_sync(0xffffffffu, sal[t], o);

        if (h == 1 && lane == 0) {
#pragma unroll
            for (int t = 0; t < TC; t++) sPart[pr * TC + t] = sal[t];
        }
    }
    __syncthreads();

    if (valid && h == 0 && lane == 0) {
        float errsum = 0.f, pmax = -3.4e38f;
#pragma unroll
        for (int t = 0; t < TC; t++) {
            float s = fmaxf(sal[t] + sPart[pr * TC + t], 1e-35f);
            float L = Mv + lg2f_(s);
            float pnew = C_AL2E - L;
            float unew = pnew - C_KK * qqv[t];
            float pold = firstDst ? C_AL2E
                                  : (__ldcg(dstU + j0 + t) + C_KK * qqv[t]);
            errsum += fabsf(pnew - pold);
            __stcg(dstU + j0 + t, unew);
            pmax = fmaxf(pmax, pnew);
        }
        atomicAdd(errSlot, errsum * C_LN2);
        atomicMax(mvDst, encf(pmax));
    }
    // trailing sync supplied by caller's grid_barrier
}

// cost = sum_ij exp(A_j + B_i - C_ij/eps) * C_ij (accumulated; /(n*m) at end)
__device__ void cost_pass(
    const float* rX, const float* rY, const float* rZ,
    const float* cX, const float* cY, const float* cZ,
    float* sU, float* sPart,
    const float* srcU, const float* srcColU,
    float* costslot, int colbase)
{
    const int tid = threadIdx.x;
    for (int t = tid; t < NN; t += TPB)
        sU[t] = __ldcg(srcU + t) + 2.0f;     // B*l2e - k|r|^2
    __syncthreads();

    const int wid = tid >> 5, lane = tid & 31;
    const int pr = wid >> 1, h = wid & 1;
    const int j0 = colbase + pr * TC;
    const bool valid = (j0 < NN);

    float a1[TC], a2[TC], qq[TC];
    if (valid) {
        float qx[TC], qy[TC], qz[TC], cp[TC];
#pragma unroll
        for (int t = 0; t < TC; t++) {
            float x = cX[j0 + t], y = cY[j0 + t], z = cZ[j0 + t];
            qq[t] = fmaf(x, x, fmaf(y, y, z * z));
            qx[t] = x * C_2K; qy[t] = y * C_2K; qz[t] = z * C_2K;
            cp[t] = __ldcg(srcColU + j0 + t) + 2.0f;   // A*l2e - k|q|^2
            a1[t] = 0.f; a2[t] = 0.f;
        }
        const float2* pX = (const float2*)rX;
        const float2* pY = (const float2*)rY;
        const float2* pZ = (const float2*)rZ;
        const float2* pU = (const float2*)sU;
        int idx = h * (NN / 4) + lane;
#pragma unroll 2
        for (int k = 0; k < NN / 128; k++, idx += 32) {
            float2 x2 = pX[idx], y2 = pY[idx], z2 = pZ[idx], u2 = pU[idx];
#pragma unroll
            for (int e = 0; e < 2; e++) {
                float x = e ? x2.y : x2.x, y = e ? y2.y : y2.x;
                float z = e ? z2.y : z2.x, u = e ? u2.y : u2.x;
                float rr = fmaf(x, x, fmaf(y, y, z * z));
#pragma unroll
                for (int t = 0; t < TC; t++) {
                    float w = fmaf(x, qx[t], fmaf(y, qy[t], fmaf(z, qz[t], u)));
                    float ev = ex2f_(w + cp[t]);
                    float Xv = fmaf(u - w, C_INVK, rr);
                    a1[t] = fmaf(ev, Xv, a1[t]);
                    a2[t] += ev;
                }
            }
        }
#pragma unroll
        for (int o = 16; o > 0; o >>= 1)
#pragma unroll
            for (int t = 0; t < TC; t++) {
                a1[t] += __shfl_xor_sync(0xffffffffu, a1[t], o);
                a2[t] += __shfl_xor_sync(0xffffffffu, a2[t], o);
            }
        if (h == 1 && lane == 0) {
#pragma unroll
            for (int t = 0; t < TC; t++) {
                sPart[pr * 8 + t] = a1[t];
                sPart[pr * 8 + 4 + t] = a2[t];
            }
        }
    }
    __syncthreads();
    if (valid && h == 0 && lane == 0) {
        float v = 0.f;
#pragma unroll
        for (int t = 0; t < TC; t++) {
            float A1 = a1[t] + sPart[pr * 8 + t];
            float A2 = a2[t] + sPart[pr * 8 + 4 + t];
            v += A1 + qq[t] * A2;
        }
        atomicAdd(costslot, v);
    }
    __syncthreads();
}

// chamfer: per own-point j, min over iter-points i of |r_i - q_j|^2
__device__ void cham_pass(
    const float* iX, const float* iY, const float* iZ,
    const float* oX, const float* oY, const float* oZ,
    float* sPart, float* accum, int colbase)
{
    const int tid = threadIdx.x, wid = tid >> 5, lane = tid & 31;
    const int pr = wid >> 1, h = wid & 1;
    const int j0 = colbase + pr * TC;
    const bool valid = (j0 < NN);

    float m[TC], qq[TC];
    if (valid) {
        float qx[TC], qy[TC], qz[TC];
#pragma unroll
        for (int t = 0; t < TC; t++) {
            float x = oX[j0 + t], y = oY[j0 + t], z = oZ[j0 + t];
            qq[t] = fmaf(x, x, fmaf(y, y, z * z));
            qx[t] = -2.f * x; qy[t] = -2.f * y; qz[t] = -2.f * z;
            m[t] = 3.4e38f;
        }
        const float2* pX = (const float2*)iX;
        const float2* pY = (const float2*)iY;
        const float2* pZ = (const float2*)iZ;
        int idx = h * (NN / 4) + lane;
        for (int k = 0; k < NN / 128; k++, idx += 32) {
            float2 x2 = pX[idx], y2 = pY[idx], z2 = pZ[idx];
#pragma unroll
            for (int e = 0; e < 2; e++) {
                float x = e ? x2.y : x2.x, y = e ? y2.y : y2.x, z = e ? z2.y : z2.x;
                float rr = fmaf(x, x, fmaf(y, y, z * z));
#pragma unroll
                for (int t = 0; t < TC; t++) {
                    float v = fmaf(x, qx[t], fmaf(y, qy[t], fmaf(z, qz[t], rr)));
                    m[t] = fminf(m[t], v);
                }
            }
        }
#pragma unroll
        for (int o = 16; o > 0; o >>= 1)
#pragma unroll
            for (int t = 0; t < TC; t++)
                m[t] = fminf(m[t], __shfl_xor_sync(0xffffffffu, m[t], o));
        if (h == 1 && lane == 0) {
#pragma unroll
            for (int t = 0; t < TC; t++) sPart[pr * TC + t] = m[t];
        }
    }
    __syncthreads();
    if (valid && h == 0 && lane == 0) {
        float s = 0.f;
#pragma unroll
        for (int t = 0; t < TC; t++)
            s += fminf(m[t], sPart[pr * TC + t]) + qq[t];
        atomicAdd(accum, s);
    }
    __syncthreads();
}

__device__ void run_sink(
    const float* rX, const float* rY, const float* rZ,
    const float* cX, const float* cY, const float* cZ,
    float* sU, float* sPart,
    float* AU, float* BU, int off, float* costslot, int b, int colbase, unsigned& lb)
{
    int it = 0;
    bool cont = true;
    while (cont) {
        half_update(rX, rY, rZ, cX, cY, cZ, sU, sPart,
                    BU, AU,
                    &g_s.mvB[off + (it == 0 ? 0 : (it - 1) * NB) + b],
                    &g_s.mvA[off + it * NB + b],
                    &g_s.errA[off + it * NB + b],
                    it == 0, it == 0, colbase);
        grid_barrier(lb);
        half_update(cX, cY, cZ, rX, rY, rZ, sU, sPart,
                    AU, BU,
                    &g_s.mvA[off + it * NB + b],
                    &g_s.mvB[off + it * NB + b],
                    &g_s.errB[off + it * NB + b],
                    false, it == 0, colbase);
        grid_barrier(lb);
        float ae = 0.f, be = 0.f;
#pragma unroll
        for (int bb = 0; bb < NB; bb++) {
            ae = fmaxf(ae, __ldcg(&g_s.errA[off + it * NB + bb]));
            be = fmaxf(be, __ldcg(&g_s.errB[off + it * NB + bb]));
        }
        ae *= (C_EPS / (float)NN);
        be *= (C_EPS / (float)NN);
        it++;
        cont = (it < NITS_K) && (ae >= C_TOL || be >= C_TOL);
    }
    cost_pass(rX, rY, rZ, cX, cY, cZ, sU, sPart, BU, AU, costslot, colbase);
}

__global__ void __launch_bounds__(TPB, 2)
emd_kernel(const float* __restrict__ preds, const float* __restrict__ gts,
           float* __restrict__ out, int out_size)
{
    extern __shared__ float sm[];
    float* sGX = sm;            float* sGY = sm + NN;     float* sGZ = sm + 2 * NN;
    float* sPX = sm + 3 * NN;   float* sPY = sm + 4 * NN; float* sPZ = sm + 5 * NN;
    float* sU  = sm + 6 * NN;
    float* sPart = sm + 7 * NN;   // 64 floats

    const int b       = blockIdx.x / CTAB;
    const int slot    = blockIdx.x % CTAB;
    const int colbase = slot * CPC;

    const float* gp = gts + (size_t)b * NN * 3;
    const float* pp = preds + (size_t)b * NN * 3;
    for (int i = threadIdx.x; i < NN; i += TPB) {
        sGX[i] = gp[3 * i + 0]; sGY[i] = gp[3 * i + 1]; sGZ[i] = gp[3 * i + 2];
        sPX[i] = pp[3 * i + 0]; sPY[i] = pp[3 * i + 1]; sPZ[i] = pp[3 * i + 2];
    }
    __syncthreads();

    unsigned lb = 0;

    cham_pass(sGX, sGY, sGZ, sPX, sPY, sPZ, sPart, &g_s.cham[b], colbase);
    cham_pass(sPX, sPY, sPZ, sGX, sGY, sGZ, sPart, &g_s.cham[NB + b], colbase);

    // run 1: C(gts, preds) — rows = gts (summed in A-half), cols = preds
    run_sink(sGX, sGY, sGZ, sPX, sPY, sPZ, sU, sPart,
             g_s.AU + b * NN, g_s.BU + b * NN, 0, &g_s.cost[b], b, colbase, lb);

    // run 2: C(preds, preds)
    run_sink(sPX, sPY, sPZ, sPX, sPY, sPZ, sU, sPart,
             g_s.AU + b * NN, g_s.BU + b * NN, NITS_K * NB, &g_s.cost[NB + b], b, colbase, lb);

    grid_barrier(lb);

    if (blockIdx.x == 0 && threadIdx.x == 0) {
        const float inv_nm = 1.0f / ((float)NN * (float)NN);
        for (int bb = 0; bb < NB && bb < out_size; bb++) {
            float c1 = __ldcg(&g_s.cost[bb]);
            float c2 = __ldcg(&g_s.cost[NB + bb]);
            out[bb] = (c1 - 0.5f * c2) * inv_nm;
        }
        if (out_size >= 5) {
            float ch = 0.f;
            for (int bb = 0; bb < NB; bb++)
                ch += __ldcg(&g_s.cham[bb]) + __ldcg(&g_s.cham[NB + bb]);
            out[4] = ch / (float)(NB * NN);
        }
    }
}

extern "C" void kernel_launch(void* const* d_in, const int* in_sizes, int n_in,
                              void* d_out, int out_size)
{
    const float* preds = (const float*)d_in[0];
    const float* gts   = (const float*)d_in[1];
    float* out = (float*)d_out;

    void* sptr = nullptr;
    cudaGetSymbolAddress(&sptr, g_s);
    cudaMemsetAsync(sptr, 0, sizeof(ScratchT), 0);

    const int smem = (int)((7 * NN + 64) * sizeof(float));
    cudaFuncSetAttribute(emd_kernel, cudaFuncAttributeMaxDynamicSharedMemorySize, smem);
    emd_kernel<<<NCTA, TPB, smem, 0>>>(preds, gts, out, out_size);
}